// round 12
// baseline (speedup 1.0000x reference)
#include <cuda_runtime.h>
#include <cuda_bf16.h>
#include <cstdint>

// z: [32,256,32,32] f32; emb: [1024,256] f32
// out: [8388608 z_q_st][32768 idx-as-f32][1 loss] f32

#define CQ 256
#define HWQ 1024
#define NPX 32768
#define KQ 1024
#define ZQ_ELEMS 8388608
#define HM 3e-3f          // margin in m = (dot - en2/2) space  (6e-3 in distance space)

typedef unsigned long long u64;

// ---- device scratch (no allocations allowed) ----
__device__ float g_en2[KQ];
__device__ float g_zt[NPX * CQ];              // z transposed [n][c], fp32 (exact)
__device__ __nv_bfloat16 g_zb[NPX * CQ];      // bf16 z, [n][c]
__device__ __nv_bfloat16 g_eb[KQ * CQ];       // bf16 emb, [k][c]
__device__ int   g_cand[NPX * 12];
__device__ unsigned char g_cnt[NPX];
__device__ float g_minv[NPX];                 // approx min of (en2 - 2dot)
__device__ int   g_idx[NPX];
__device__ float g_part[512];

__device__ __forceinline__ void cpasync16(uint32_t dst, const void* src) {
    asm volatile("cp.async.cg.shared.global [%0], [%1], 16;" :: "r"(dst), "l"(src));
}

// ======================= Kernel: transpose z -> fp32 + bf16 =======================
__global__ __launch_bounds__(256) void vq_split(const float* __restrict__ z) {
    extern __shared__ float zs[];               // [256][65]  ([c][px])
    int t = threadIdx.x, blk = blockIdx.x;
    int bb = blk >> 4, hw0 = (blk & 15) << 6;
    const float* zbase = z + ((long)bb << 18) + hw0;
    const float4* src = (const float4*)(zbase + (long)t * HWQ);
    #pragma unroll
    for (int i = 0; i < 16; i++) {
        float4 v = src[i];
        float* d = zs + t * 65 + i * 4;
        d[0] = v.x; d[1] = v.y; d[2] = v.z; d[3] = v.w;
    }
    __syncthreads();
    int px = t & 63, cq = t >> 6;
    long n = (long)bb * HWQ + hw0 + px;
    float* zt = g_zt + n * CQ + cq * 64;
    __nv_bfloat16* zb = g_zb + n * CQ + cq * 64;
    #pragma unroll
    for (int i = 0; i < 16; i++) {
        int c = cq * 64 + i * 4;
        float a = zs[c * 65 + px], b = zs[(c + 1) * 65 + px];
        float e = zs[(c + 2) * 65 + px], f = zs[(c + 3) * 65 + px];
        float4 v = {a, b, e, f};
        *(float4*)(zt + i * 4) = v;
        *(__nv_bfloat162*)(zb + i * 4)     = __floats2bfloat162_rn(a, b);
        *(__nv_bfloat162*)(zb + i * 4 + 2) = __floats2bfloat162_rn(e, f);
    }
}

// ======================= Kernel: ||e||^2 + bf16 emb =======================
__global__ void vq_en2eb(const float* __restrict__ emb) {
    int warp = (blockIdx.x * blockDim.x + threadIdx.x) >> 5, lane = threadIdx.x & 31;
    for (int i = 0; i < 16; i++) {
        int k = warp * 16 + i;
        const float* row = emb + (long)k * CQ;
        float s = 0.0f;
        #pragma unroll
        for (int j = 0; j < 8; j++) {
            float v = row[lane + 32 * j];
            g_eb[k * CQ + lane + 32 * j] = __float2bfloat16(v);
            s = __fadd_rn(s, __fmul_rn(v, v));
        }
        #pragma unroll
        for (int off = 16; off; off >>= 1)
            s = __fadd_rn(s, __shfl_xor_sync(0xffffffffu, s, off));
        if (lane == 0) g_en2[k] = s;
    }
}

// ======================= Kernel: HMMA approx + candidate selection =======================
// CTA = 256 pixels x 1024 codes. 8 warps: warp w = pixels [w*32, w*32+32).
// A resident in smem (256px x 256c bf16, row stride 264); B = 64-code chunks,
// double-buffered cp.async. mma.sync.m16n8k16.row.col (D = A.B^T).
// Epilogue is register-lean: no mval buffer (recompute from acc), so the
// 64-reg accumulator tile never spills (R10's 8.8ms was epilogue-spill-driven).
#define BSTR 264
#define A_OFF 0
#define B_OFF 135168                 // 256*264*2
#define BBUF  33792                  // 64*264*2
#define E2_OFF  202752               // B_OFF + 2*BBUF
#define CNT_OFF 206848
#define RM_OFF  207872
#define HMMA_SMEM 208896

__device__ __forceinline__ void fillB(uint32_t smb, int chunk, int buf, int t) {
    int kb = chunk * 64;
    #pragma unroll
    for (int i = 0; i < 8; i++) {
        int idx = i * 256 + t;
        int row = idx >> 5, cq = idx & 31;
        uint32_t dst = smb + B_OFF + buf * BBUF + row * (BSTR * 2) + cq * 16;
        cpasync16(dst, g_eb + (size_t)(kb + row) * CQ + cq * 8);
    }
}

__global__ __launch_bounds__(256, 1) void vq_hmma(int dummy) {
    extern __shared__ __align__(16) char smc[];
    uint32_t smb = (uint32_t)__cvta_generic_to_shared(smc);
    float* en2h = (float*)(smc + E2_OFF);
    int*   scnt = (int*)(smc + CNT_OFF);
    float* srm  = (float*)(smc + RM_OFF);

    const int t = threadIdx.x, w = t >> 5, lane = t & 31;
    const int px0 = blockIdx.x * 256;

    for (int i = t; i < 1024; i += 256) en2h[i] = 0.5f * g_en2[i];
    scnt[t] = 0;

    // A: 256 rows x 512B = 8192 16B chunks
    #pragma unroll
    for (int i = 0; i < 32; i++) {
        int idx = i * 256 + t;
        int row = idx >> 5, cq = idx & 31;
        cpasync16(smb + A_OFF + row * (BSTR * 2) + cq * 16,
                  g_zb + (size_t)(px0 + row) * CQ + cq * 8);
    }
    fillB(smb, 0, 0, t);
    asm volatile("cp.async.commit_group;" ::: "memory");
    fillB(smb, 1, 1, t);
    asm volatile("cp.async.commit_group;" ::: "memory");

    // ldmatrix lane addressing (k-contiguous, .row/.col frags, non-trans)
    const int arow = (lane & 7) + ((lane >> 3) & 1) * 8;   // A: x4
    const int acol = (lane >> 4) * 8;
    const int bg   = lane >> 3;          // B x4: matrix group 0..3
    const int brow = lane & 7;
    // matrices (nt_pair: nt0+g>>1, k-half: (g&1)*8)

    float rm[4] = {-3.4e38f, -3.4e38f, -3.4e38f, -3.4e38f};
    const int q  = lane >> 2;
    const int c2 = (lane & 3) * 2;

    for (int ic = 0; ic < 16; ic++) {
        if (ic < 15) asm volatile("cp.async.wait_group 1;" ::: "memory");
        else         asm volatile("cp.async.wait_group 0;" ::: "memory");
        __syncthreads();

        const int buf = ic & 1, kb = ic * 64;
        float acc[2][8][4];
        #pragma unroll
        for (int mt = 0; mt < 2; mt++)
            #pragma unroll
            for (int nt = 0; nt < 8; nt++)
                #pragma unroll
                for (int j = 0; j < 4; j++) acc[mt][nt][j] = 0.0f;

        #pragma unroll 2
        for (int ks = 0; ks < 16; ks++) {
            uint32_t a[2][4], b[8][2];
            #pragma unroll
            for (int mt = 0; mt < 2; mt++) {
                uint32_t ad = smb + A_OFF + (w * 32 + mt * 16 + arow) * (BSTR * 2)
                            + (ks * 16 + acol) * 2;
                asm volatile("ldmatrix.sync.aligned.m8n8.x4.shared.b16 {%0,%1,%2,%3}, [%4];"
                             : "=r"(a[mt][0]), "=r"(a[mt][1]), "=r"(a[mt][2]), "=r"(a[mt][3])
                             : "r"(ad));
            }
            #pragma unroll
            for (int np = 0; np < 4; np++) {   // nt pair (2 n-tiles per ldmatrix.x4)
                uint32_t bd = smb + B_OFF + buf * BBUF
                            + ((np * 2 + (bg >> 1)) * 8 + brow) * (BSTR * 2)
                            + (ks * 16 + (bg & 1) * 8) * 2;
                asm volatile("ldmatrix.sync.aligned.m8n8.x4.shared.b16 {%0,%1,%2,%3}, [%4];"
                             : "=r"(b[np * 2][0]), "=r"(b[np * 2][1]),
                               "=r"(b[np * 2 + 1][0]), "=r"(b[np * 2 + 1][1])
                             : "r"(bd));
            }
            #pragma unroll
            for (int mt = 0; mt < 2; mt++)
                #pragma unroll
                for (int nt = 0; nt < 8; nt++)
                    asm volatile(
                        "mma.sync.aligned.m16n8k16.row.col.f32.bf16.bf16.f32 "
                        "{%0,%1,%2,%3}, {%4,%5,%6,%7}, {%8,%9}, {%0,%1,%2,%3};"
                        : "+f"(acc[mt][nt][0]), "+f"(acc[mt][nt][1]),
                          "+f"(acc[mt][nt][2]), "+f"(acc[mt][nt][3])
                        : "r"(a[mt][0]), "r"(a[mt][1]), "r"(a[mt][2]), "r"(a[mt][3]),
                          "r"(b[nt][0]), "r"(b[nt][1]));
        }

        // ---- epilogue pass 1: chunk max of m = dot - en2/2 (no mval buffer)
        float cmax[4] = {-3.4e38f, -3.4e38f, -3.4e38f, -3.4e38f};
        #pragma unroll
        for (int mt = 0; mt < 2; mt++)
            #pragma unroll
            for (int nt = 0; nt < 8; nt++) {
                float e0 = en2h[kb + nt * 8 + c2];
                float e1 = en2h[kb + nt * 8 + c2 + 1];
                cmax[mt * 2]     = fmaxf(cmax[mt * 2],
                                   fmaxf(acc[mt][nt][0] - e0, acc[mt][nt][1] - e1));
                cmax[mt * 2 + 1] = fmaxf(cmax[mt * 2 + 1],
                                   fmaxf(acc[mt][nt][2] - e0, acc[mt][nt][3] - e1));
            }
        #pragma unroll
        for (int j = 0; j < 4; j++) {
            float v = cmax[j];
            v = fmaxf(v, __shfl_xor_sync(0xffffffffu, v, 1));
            v = fmaxf(v, __shfl_xor_sync(0xffffffffu, v, 2));
            rm[j] = fmaxf(rm[j], v);
        }
        // ---- epilogue pass 2: candidates (recompute m from live acc)
        #pragma unroll
        for (int mt = 0; mt < 2; mt++)
            #pragma unroll
            for (int nt = 0; nt < 8; nt++) {
                float e0 = en2h[kb + nt * 8 + c2];
                float e1 = en2h[kb + nt * 8 + c2 + 1];
                #pragma unroll
                for (int j = 0; j < 4; j++) {
                    float m = acc[mt][nt][j] - ((j & 1) ? e1 : e0);
                    int ji = mt * 2 + (j >> 1);
                    if (m > rm[ji] - HM) {
                        int pxl = w * 32 + mt * 16 + (j >> 1) * 8 + q;
                        int code = kb + nt * 8 + c2 + (j & 1);
                        int pos = atomicAdd(&scnt[pxl], 1);
                        if (pos < 12) g_cand[(size_t)(px0 + pxl) * 12 + pos] = code;
                    }
                }
            }

        __syncthreads();                     // all reads of buf done before refill
        if (ic + 2 < 16) {
            fillB(smb, ic + 2, buf, t);      // (ic+2)&1 == ic&1
            asm volatile("cp.async.commit_group;" ::: "memory");
        }
    }

    // write per-pixel results
    if ((lane & 3) == 0) {
        #pragma unroll
        for (int j = 0; j < 4; j++) {
            int pxl = w * 32 + (j >> 1) * 16 + (j & 1) * 8 + q;
            srm[pxl] = rm[(j >> 1) * 2 + (j & 1)];
        }
    }
    __syncthreads();
    {
        int n = px0 + t;
        int cnt = scnt[t];
        g_cnt[n] = (unsigned char)(cnt > 12 ? 200 : cnt);
        g_minv[n] = -2.0f * srm[t];
    }
}

// ======================= Kernel: exact rescore (reference-bit-exact) =======================
__device__ __forceinline__ float exact_dot(const float* __restrict__ zr,
                                           const float* __restrict__ er) {
    float dot = 0.0f;
    #pragma unroll 8
    for (int c = 0; c < CQ; c++) dot = fmaf(zr[c], er[c], dot);
    return dot;
}

__global__ __launch_bounds__(256) void vq_exact(const float* __restrict__ emb,
                                                float* __restrict__ out_idx) {
    int n = blockIdx.x * 256 + threadIdx.x;
    const float* zr = g_zt + (long)n * CQ;
    float zn2 = 0.0f;
    #pragma unroll 8
    for (int c = 0; c < CQ; c++) zn2 = fmaf(zr[c], zr[c], zn2);

    int cnt = g_cnt[n];
    float bv = 3.402823466e38f;
    int bi = 0x7fffffff;
    bool full = (cnt > 12);
    if (!full) {
        for (int j = 0; j < cnt; j++) {
            int k = g_cand[(size_t)n * 12 + j];
            float dot = exact_dot(zr, emb + (long)k * CQ);
            float s0 = __fadd_rn(zn2, g_en2[k]);
            float v = __fadd_rn(s0, __fmul_rn(-2.0f, dot));
            if (v < bv || (v == bv && k < bi)) { bv = v; bi = k; }
        }
        if (fabsf(__fadd_rn(bv, -zn2) - g_minv[n]) > 0.02f) full = true;  // sanity valve
    }
    if (full) {
        bv = 3.402823466e38f; bi = 0x7fffffff;
        for (int k = 0; k < KQ; k++) {
            float dot = exact_dot(zr, emb + (long)k * CQ);
            float s0 = __fadd_rn(zn2, g_en2[k]);
            float v = __fadd_rn(s0, __fmul_rn(-2.0f, dot));
            if (v < bv || (v == bv && k < bi)) { bv = v; bi = k; }
        }
    }
    g_idx[n] = bi;
    out_idx[n] = (float)bi;
}

// ======================= Kernel: gather + STE + loss partials =======================
__global__ __launch_bounds__(256) void vq_gather(const float* __restrict__ z,
                                                 const float* __restrict__ emb,
                                                 float* __restrict__ outz) {
    extern __shared__ float srows[];           // [64][259]
    __shared__ int idxs[64];
    __shared__ float ws[8];
    int t = threadIdx.x, blk = blockIdx.x;
    int bb = blk >> 4, hw0 = (blk & 15) << 6;
    if (t < 64) idxs[t] = g_idx[bb * HWQ + hw0 + t];
    __syncthreads();
    {
        int r = t >> 2, part = t & 3;
        const float4* er = (const float4*)(emb + (long)idxs[r] * CQ + part * 64);
        float* d = srows + r * 259 + part * 64;
        #pragma unroll
        for (int i = 0; i < 16; i++) {
            float4 v = er[i];
            d[i * 4] = v.x; d[i * 4 + 1] = v.y; d[i * 4 + 2] = v.z; d[i * 4 + 3] = v.w;
        }
    }
    __syncthreads();
    int px = t & 63, c0 = t >> 6;
    const float* zb = z + ((long)bb << 18) + hw0;
    float* ob = outz + ((long)bb << 18) + hw0;
    float acc = 0.0f;
    #pragma unroll 4
    for (int i = 0; i < 64; i++) {
        int c = i * 4 + c0;
        float zv = zb[(long)c * HWQ + px];
        float qv = srows[px * 259 + c];
        float d0 = __fadd_rn(qv, -zv);
        ob[(long)c * HWQ + px] = __fadd_rn(zv, d0);     // == z + sg(z_q - z)
        acc = fmaf(d0, d0, acc);
    }
    #pragma unroll
    for (int off = 16; off; off >>= 1)
        acc += __shfl_xor_sync(0xffffffffu, acc, off);
    if ((t & 31) == 0) ws[t >> 5] = acc;
    __syncthreads();
    if (t == 0) {
        float tot = 0.0f;
        #pragma unroll
        for (int i = 0; i < 8; i++) tot += ws[i];
        g_part[blk] = tot;
    }
}

// ======================= Kernel: final loss =======================
__global__ void vq_loss(float* __restrict__ out) {
    __shared__ double red[256];
    double s = 0.0;
    for (int i = threadIdx.x; i < 512; i += 256) s += (double)g_part[i];
    red[threadIdx.x] = s;
    __syncthreads();
    for (int st = 128; st; st >>= 1) {
        if (threadIdx.x < st) red[threadIdx.x] += red[threadIdx.x + st];
        __syncthreads();
    }
    if (threadIdx.x == 0) {
        float m = (float)(red[0] / 8388608.0);
        out[ZQ_ELEMS + NPX] = 0.25f * m + m;
    }
}

// ======================= launcher =======================
extern "C" void kernel_launch(void* const* d_in, const int* in_sizes, int n_in,
                              void* d_out, int out_size) {
    const float* z   = (const float*)d_in[0];
    const float* emb = (const float*)d_in[1];
    float* out = (float*)d_out;

    cudaFuncSetAttribute(vq_split,  cudaFuncAttributeMaxDynamicSharedMemorySize, 256 * 65 * 4);
    cudaFuncSetAttribute(vq_hmma,   cudaFuncAttributeMaxDynamicSharedMemorySize, HMMA_SMEM);
    cudaFuncSetAttribute(vq_gather, cudaFuncAttributeMaxDynamicSharedMemorySize, 64 * 259 * 4);

    vq_split<<<512, 256, 256 * 65 * 4>>>(z);
    vq_en2eb<<<8, 256>>>(emb);
    vq_hmma<<<128, 256, HMMA_SMEM>>>(0);
    vq_exact<<<128, 256>>>(emb, out + ZQ_ELEMS);
    vq_gather<<<512, 256, 64 * 259 * 4>>>(z, emb, out);
    vq_loss<<<1, 256>>>(out);
}

// round 13
// speedup vs baseline: 21.9030x; 21.9030x over previous
#include <cuda_runtime.h>
#include <cuda_bf16.h>
#include <cstdint>

// z: [32,256,32,32] f32; emb: [1024,256] f32
// out: [8388608 z_q_st][32768 idx-as-f32][1 loss] f32

#define CQ      256
#define HWQ     1024
#define NPX     32768
#define KQ      1024
#define ZQ_ELEMS 8388608
#define NUNITS  2048          // 512 tiles x 4 kb-blocks
#define NWORK   296           // 2 CTAs x 148 SMs, persistent

typedef unsigned long long u64;

// ---- device scratch (no allocations allowed) ----
__device__ float g_en2[KQ];
__device__ float g_zn2[NPX];
__device__ float g_bestv[NPX * 4];
__device__ int   g_besti[NPX * 4];
__device__ float g_part[512];
__device__ int   g_unit;

// ---------------------------------------------------------------------------
// Kernel 1: ||e_k||^2 (bit-identical chain to the 477us passing kernel)
// + unit-counter reset for the persistent stealer.
// ---------------------------------------------------------------------------
__global__ void vq_en2(const float* __restrict__ emb) {
    if (blockIdx.x == 0 && threadIdx.x == 0) g_unit = 0;
    int warp = (blockIdx.x * blockDim.x + threadIdx.x) >> 5;   // 0..63
    int lane = threadIdx.x & 31;
    for (int i = 0; i < 16; i++) {
        int k = warp * 16 + i;
        const float* row = emb + (long)k * CQ;
        float s = 0.0f;
        #pragma unroll
        for (int j = 0; j < 8; j++) {
            float v = row[lane + 32 * j];
            s = __fadd_rn(s, __fmul_rn(v, v));
        }
        #pragma unroll
        for (int off = 16; off; off >>= 1)
            s = __fadd_rn(s, __shfl_xor_sync(0xffffffffu, s, off));
        if (lane == 0) g_en2[k] = s;
    }
}

// ---------------------------------------------------------------------------
// Kernel 2: ||z_n||^2 — per-pixel ascending-c fmaf chain, IDENTICAL sequence
// to the R7 kernel's inline zsq (fma.rn.f32x2 lanes == independent scalar
// fmaf chains over c = 0..255). Coalesced: warp = 32 consecutive hw.
// ---------------------------------------------------------------------------
__global__ __launch_bounds__(256) void vq_zn2(const float* __restrict__ z) {
    int n = blockIdx.x * 256 + threadIdx.x;
    int bb = n >> 10, hw = n & 1023;
    const float* p = z + ((long)bb << 18) + hw;
    float acc = 0.0f;
    #pragma unroll 8
    for (int c = 0; c < CQ; c++) {
        float v = p[(long)c << 10];
        acc = fmaf(v, v, acc);
    }
    g_zn2[n] = acc;
}

// ---------------------------------------------------------------------------
// Kernel 3: persistent unit-stealing distance-GEMM + per-unit argmin.
// Unit = (64px tile, 256-code kb block) -> 2048 units over 296 workers
// (98.9% balance vs 86.5% for the static 512-CTA grid).
// Compute chains, fold rounding (d = fl(fl(zn2+en2) - fl(2*dot))), code
// ordering and tie rules are bit-identical to the 477us passing kernel.
// ---------------------------------------------------------------------------
#define ZS0 0
#define ZS1 2048
#define ES0 4096
#define ESB 9216          // 256 * 36
#define SMEM_FLOATS 22528
#define SMEM_BYTES (SMEM_FLOATS * 4)   // 90112

__device__ __forceinline__ void cpasync16(uint32_t dst, const void* src) {
    asm volatile("cp.async.cg.shared.global [%0], [%1], 16;" :: "r"(dst), "l"(src));
}

__device__ __forceinline__ void fill_stage(uint32_t sm32, const float* zbase,
                                           const float* emb, int kb, int cb,
                                           int b, int t) {
    // z: 32 rows x 64 floats
    #pragma unroll
    for (int i = 0; i < 2; i++) {
        int idx = t + (i << 8);
        int cl = idx >> 4;
        int q  = (idx & 15) << 2;
        const float* src = zbase + (long)(cb + cl) * HWQ + q;
        uint32_t dst = sm32 + (uint32_t)(((b ? ZS1 : ZS0) + cl * 64 + q) << 2);
        cpasync16(dst, src);
    }
    // e: 256 rows x 32 floats (row stride 36)
    #pragma unroll
    for (int i = 0; i < 8; i++) {
        int idx = t + (i << 8);
        int k = idx >> 3;
        int q = (idx & 7) << 2;
        const float* src = emb + (long)(kb + k) * CQ + cb + q;
        uint32_t dst = sm32 + (uint32_t)((ES0 + b * ESB + k * 36 + q) << 2);
        cpasync16(dst, src);
    }
}

__device__ __forceinline__ void compute_stage(const float* __restrict__ zsp,
                                              const float* __restrict__ ep0,
                                              int pxA, int pxB, u64 acc[4][8]) {
    #pragma unroll 4
    for (int c = 0; c < 32; c++) {
        const float* zr = zsp + c * 64;
        ulonglong2 za = *(const ulonglong2*)(zr + pxA);
        ulonglong2 zb = *(const ulonglong2*)(zr + pxB);
        float ef[8];
        #pragma unroll
        for (int j = 0; j < 8; j++) ef[j] = ep0[j * (32 * 36) + c];
        #pragma unroll
        for (int j = 0; j < 8; j++) {
            u64 ed;
            asm("mov.b64 %0, {%1, %1};" : "=l"(ed) : "f"(ef[j]));
            asm("fma.rn.f32x2 %0, %1, %2, %0;" : "+l"(acc[0][j]) : "l"(za.x), "l"(ed));
            asm("fma.rn.f32x2 %0, %1, %2, %0;" : "+l"(acc[1][j]) : "l"(za.y), "l"(ed));
            asm("fma.rn.f32x2 %0, %1, %2, %0;" : "+l"(acc[2][j]) : "l"(zb.x), "l"(ed));
            asm("fma.rn.f32x2 %0, %1, %2, %0;" : "+l"(acc[3][j]) : "l"(zb.y), "l"(ed));
        }
    }
}

__global__ void __launch_bounds__(256, 2)
vq_unit(const float* __restrict__ z, const float* __restrict__ emb) {
    extern __shared__ float smem[];
    uint32_t sm32 = (uint32_t)__cvta_generic_to_shared(smem);
    __shared__ int s_u;

    const int t  = threadIdx.x;
    const int pg = t & 7;
    const int kg = t >> 3;
    const int pxA = pg * 4;
    const int pxB = 32 + pg * 4;

    float* redv = smem;                    // [32][64]  (reused post-compute)
    int*   redi = (int*)(smem + 2048);

    while (true) {
        __syncthreads();                   // previous iter's smem reads done
        if (t == 0) s_u = atomicAdd(&g_unit, 1);
        __syncthreads();
        int u = s_u;
        if (u >= NUNITS) break;

        const int tile = u >> 2;
        const int kb   = (u & 3) << 8;
        const int bb   = tile >> 4;
        const int hw0  = (tile & 15) << 6;
        const float* zbase = z + ((long)bb << 18) + hw0;

        // per-pixel ||z||^2 (reference-chain values)
        float zn2p[8];
        #pragma unroll
        for (int j = 0; j < 8; j++) {
            int px = (j < 4) ? (pxA + j) : (pxB + j - 4);
            zn2p[j] = g_zn2[tile * 64 + px];
        }

        u64 acc[4][8];
        #pragma unroll
        for (int pp = 0; pp < 4; pp++)
            #pragma unroll
            for (int j = 0; j < 8; j++) acc[pp][j] = 0ull;

        fill_stage(sm32, zbase, emb, kb, 0, 0, t);
        asm volatile("cp.async.commit_group;" ::: "memory");

        for (int s = 0; s < 8; s++) {
            asm volatile("cp.async.wait_group 0;" ::: "memory");
            __syncthreads();
            if (s < 7) {
                fill_stage(sm32, zbase, emb, kb, (s + 1) << 5, (s + 1) & 1, t);
                asm volatile("cp.async.commit_group;" ::: "memory");
            }
            const int b = s & 1;
            compute_stage(smem + (b ? ZS1 : ZS0), smem + ES0 + b * ESB + kg * 36,
                          pxA, pxB, acc);
        }

        // fold: d = fl( fl(zn2+en2) - fl(2*dot) ); codes kb+kg+32j ascending
        float bestv[8];
        int   besti[8];
        #pragma unroll
        for (int i = 0; i < 8; i++) { bestv[i] = 3.402823466e38f; besti[i] = 0x7fffffff; }
        #pragma unroll
        for (int j = 0; j < 8; j++) {
            int code = kb + kg + 32 * j;
            float e2 = g_en2[code];
            #pragma unroll
            for (int pp = 0; pp < 4; pp++) {
                float lo, hi;
                asm("mov.b64 {%0, %1}, %2;" : "=f"(lo), "=f"(hi) : "l"(acc[pp][j]));
                int i2 = pp * 2;
                float s0 = __fadd_rn(zn2p[i2],     e2);
                float s1 = __fadd_rn(zn2p[i2 + 1], e2);
                float v0 = __fadd_rn(s0, __fmul_rn(-2.0f, lo));
                float v1 = __fadd_rn(s1, __fmul_rn(-2.0f, hi));
                if (v0 < bestv[i2])     { bestv[i2]     = v0; besti[i2]     = code; }
                if (v1 < bestv[i2 + 1]) { bestv[i2 + 1] = v1; besti[i2 + 1] = code; }
            }
        }

        // cross-kg reduction; tie -> lowest index (same as passing kernel)
        __syncthreads();
        #pragma unroll
        for (int j = 0; j < 8; j++) {
            int px = (j < 4) ? (pxA + j) : (pxB + j - 4);
            redv[kg * 64 + px] = bestv[j];
            redi[kg * 64 + px] = besti[j];
        }
        __syncthreads();
        if (t < 64) {
            float bv = redv[t];
            int   bi = redi[t];
            #pragma unroll 4
            for (int g = 1; g < 32; g++) {
                float v = redv[g * 64 + t];
                int   i = redi[g * 64 + t];
                if (v < bv || (v == bv && i < bi)) { bv = v; bi = i; }
            }
            int n = tile * 64 + t;
            g_bestv[n * 4 + (u & 3)] = bv;
            g_besti[n * 4 + (u & 3)] = bi;
        }
    }
}

// ---------------------------------------------------------------------------
// Kernel 4: cross-kb final argmin + gather + STE + loss partials.
// Ascending kb with strict < keeps the lowest index on rounded ties
// (higher kb => strictly higher code index).
// ---------------------------------------------------------------------------
__global__ __launch_bounds__(256) void vq_gather(const float* __restrict__ z,
                                                 const float* __restrict__ emb,
                                                 float* __restrict__ outz,
                                                 float* __restrict__ out_idx) {
    extern __shared__ float srows[];           // [64][259]
    __shared__ int idxs[64];
    __shared__ float ws[8];
    int t = threadIdx.x, blk = blockIdx.x;
    int bb = blk >> 4, hw0 = (blk & 15) << 6;
    if (t < 64) {
        int n = blk * 64 + t;                  // == bb*HWQ + hw0 + t
        float bv = g_bestv[n * 4];
        int   bi = g_besti[n * 4];
        #pragma unroll
        for (int s = 1; s < 4; s++) {
            float v = g_bestv[n * 4 + s];
            int   i = g_besti[n * 4 + s];
            if (v < bv) { bv = v; bi = i; }
        }
        idxs[t] = bi;
        out_idx[n] = (float)bi;
    }
    __syncthreads();
    {
        int r = t >> 2, part = t & 3;
        const float4* er = (const float4*)(emb + (long)idxs[r] * CQ + part * 64);
        float* d = srows + r * 259 + part * 64;
        #pragma unroll
        for (int i = 0; i < 16; i++) {
            float4 v = er[i];
            d[i * 4] = v.x; d[i * 4 + 1] = v.y; d[i * 4 + 2] = v.z; d[i * 4 + 3] = v.w;
        }
    }
    __syncthreads();
    int px = t & 63, c0 = t >> 6;
    const float* zb = z + ((long)bb << 18) + hw0;
    float* ob = outz + ((long)bb << 18) + hw0;
    float acc = 0.0f;
    #pragma unroll 4
    for (int i = 0; i < 64; i++) {
        int c = i * 4 + c0;
        float zv = zb[(long)c * HWQ + px];
        float qv = srows[px * 259 + c];
        float d0 = __fadd_rn(qv, -zv);
        ob[(long)c * HWQ + px] = __fadd_rn(zv, d0);     // == z + sg(z_q - z)
        acc = fmaf(d0, d0, acc);
    }
    #pragma unroll
    for (int off = 16; off; off >>= 1)
        acc += __shfl_xor_sync(0xffffffffu, acc, off);
    if ((t & 31) == 0) ws[t >> 5] = acc;
    __syncthreads();
    if (t == 0) {
        float tot = 0.0f;
        #pragma unroll
        for (int i = 0; i < 8; i++) tot += ws[i];
        g_part[blk] = tot;
    }
}

// ---------------------------------------------------------------------------
// Kernel 5: deterministic final loss (double accumulation).
// ---------------------------------------------------------------------------
__global__ void vq_loss(float* __restrict__ out) {
    __shared__ double red[256];
    double s = 0.0;
    for (int i = threadIdx.x; i < 512; i += 256) s += (double)g_part[i];
    red[threadIdx.x] = s;
    __syncthreads();
    for (int st = 128; st; st >>= 1) {
        if (threadIdx.x < st) red[threadIdx.x] += red[threadIdx.x + st];
        __syncthreads();
    }
    if (threadIdx.x == 0) {
        float m = (float)(red[0] / 8388608.0);
        out[ZQ_ELEMS + NPX] = 0.25f * m + m;
    }
}

// ---------------------------------------------------------------------------
extern "C" void kernel_launch(void* const* d_in, const int* in_sizes, int n_in,
                              void* d_out, int out_size) {
    const float* z   = (const float*)d_in[0];
    const float* emb = (const float*)d_in[1];
    float* out = (float*)d_out;

    cudaFuncSetAttribute(vq_unit, cudaFuncAttributeMaxDynamicSharedMemorySize,
                         SMEM_BYTES);
    cudaFuncSetAttribute(vq_gather, cudaFuncAttributeMaxDynamicSharedMemorySize,
                         64 * 259 * 4);

    vq_en2<<<8, 256>>>(emb);
    vq_zn2<<<128, 256>>>(z);
    vq_unit<<<NWORK, 256, SMEM_BYTES>>>(z, emb);
    vq_gather<<<512, 256, 64 * 259 * 4>>>(z, emb, out, out + ZQ_ELEMS);
    vq_loss<<<1, 256>>>(out);
}

// round 14
// speedup vs baseline: 24.5108x; 1.1191x over previous
#include <cuda_runtime.h>
#include <cuda_bf16.h>
#include <cstdint>

// z: [32,256,32,32] f32; emb: [1024,256] f32
// out: [8388608 z_q_st][32768 idx-as-f32][1 loss] f32

#define CQ      256
#define HWQ     1024
#define NPX     32768
#define KQ      1024
#define ZQ_ELEMS 8388608
#define NUNITS  2048          // 512 tiles x 4 kb-blocks
#define NWORK   296           // 2 CTAs x 148 SMs, persistent

typedef unsigned long long u64;

// ---- device scratch (no allocations allowed) ----
__device__ float g_en2[KQ];
__device__ float g_zn2[NPX];
__device__ float g_bestv[NPX * 4];
__device__ int   g_besti[NPX * 4];
__device__ float g_part[1024];
__device__ int   g_unit;
__device__ int   g_done;

// ---------------------------------------------------------------------------
// Kernel 1 (merged): blocks 0-7 -> ||e_k||^2 (chain identical to passing
// kernel); blocks 8-135 -> ||z_n||^2 (sequential ascending-c fmaf chain,
// value-identical to R12; unroll 16 for MLP). Also resets counters.
// ---------------------------------------------------------------------------
__global__ void vq_pre(const float* __restrict__ emb, const float* __restrict__ z) {
    if (blockIdx.x == 0 && threadIdx.x == 0) { g_unit = 0; g_done = 0; }
    if (blockIdx.x < 8) {
        int warp = (blockIdx.x * blockDim.x + threadIdx.x) >> 5;   // 0..63
        int lane = threadIdx.x & 31;
        for (int i = 0; i < 16; i++) {
            int k = warp * 16 + i;
            const float* row = emb + (long)k * CQ;
            float s = 0.0f;
            #pragma unroll
            for (int j = 0; j < 8; j++) {
                float v = row[lane + 32 * j];
                s = __fadd_rn(s, __fmul_rn(v, v));
            }
            #pragma unroll
            for (int off = 16; off; off >>= 1)
                s = __fadd_rn(s, __shfl_xor_sync(0xffffffffu, s, off));
            if (lane == 0) g_en2[k] = s;
        }
    } else {
        int n = (blockIdx.x - 8) * 256 + threadIdx.x;
        int bb = n >> 10, hw = n & 1023;
        const float* p = z + ((long)bb << 18) + hw;
        float acc = 0.0f;
        #pragma unroll 16
        for (int c = 0; c < CQ; c++) {
            float v = p[(long)c << 10];
            acc = fmaf(v, v, acc);
        }
        g_zn2[n] = acc;
    }
}

// ---------------------------------------------------------------------------
// Kernel 2: persistent unit-stealing distance-GEMM + per-unit argmin.
// (unchanged from the 403.9us passing kernel — at the FFMA2 RF-bank floor)
// ---------------------------------------------------------------------------
#define ZS0 0
#define ZS1 2048
#define ES0 4096
#define ESB 9216          // 256 * 36
#define SMEM_FLOATS 22528
#define SMEM_BYTES (SMEM_FLOATS * 4)   // 90112

__device__ __forceinline__ void cpasync16(uint32_t dst, const void* src) {
    asm volatile("cp.async.cg.shared.global [%0], [%1], 16;" :: "r"(dst), "l"(src));
}

__device__ __forceinline__ void fill_stage(uint32_t sm32, const float* zbase,
                                           const float* emb, int kb, int cb,
                                           int b, int t) {
    #pragma unroll
    for (int i = 0; i < 2; i++) {
        int idx = t + (i << 8);
        int cl = idx >> 4;
        int q  = (idx & 15) << 2;
        const float* src = zbase + (long)(cb + cl) * HWQ + q;
        uint32_t dst = sm32 + (uint32_t)(((b ? ZS1 : ZS0) + cl * 64 + q) << 2);
        cpasync16(dst, src);
    }
    #pragma unroll
    for (int i = 0; i < 8; i++) {
        int idx = t + (i << 8);
        int k = idx >> 3;
        int q = (idx & 7) << 2;
        const float* src = emb + (long)(kb + k) * CQ + cb + q;
        uint32_t dst = sm32 + (uint32_t)((ES0 + b * ESB + k * 36 + q) << 2);
        cpasync16(dst, src);
    }
}

__device__ __forceinline__ void compute_stage(const float* __restrict__ zsp,
                                              const float* __restrict__ ep0,
                                              int pxA, int pxB, u64 acc[4][8]) {
    #pragma unroll 4
    for (int c = 0; c < 32; c++) {
        const float* zr = zsp + c * 64;
        ulonglong2 za = *(const ulonglong2*)(zr + pxA);
        ulonglong2 zb = *(const ulonglong2*)(zr + pxB);
        float ef[8];
        #pragma unroll
        for (int j = 0; j < 8; j++) ef[j] = ep0[j * (32 * 36) + c];
        #pragma unroll
        for (int j = 0; j < 8; j++) {
            u64 ed;
            asm("mov.b64 %0, {%1, %1};" : "=l"(ed) : "f"(ef[j]));
            asm("fma.rn.f32x2 %0, %1, %2, %0;" : "+l"(acc[0][j]) : "l"(za.x), "l"(ed));
            asm("fma.rn.f32x2 %0, %1, %2, %0;" : "+l"(acc[1][j]) : "l"(za.y), "l"(ed));
            asm("fma.rn.f32x2 %0, %1, %2, %0;" : "+l"(acc[2][j]) : "l"(zb.x), "l"(ed));
            asm("fma.rn.f32x2 %0, %1, %2, %0;" : "+l"(acc[3][j]) : "l"(zb.y), "l"(ed));
        }
    }
}

__global__ void __launch_bounds__(256, 2)
vq_unit(const float* __restrict__ z, const float* __restrict__ emb) {
    extern __shared__ float smem[];
    uint32_t sm32 = (uint32_t)__cvta_generic_to_shared(smem);
    __shared__ int s_u;

    const int t  = threadIdx.x;
    const int pg = t & 7;
    const int kg = t >> 3;
    const int pxA = pg * 4;
    const int pxB = 32 + pg * 4;

    float* redv = smem;                    // [32][64]  (reused post-compute)
    int*   redi = (int*)(smem + 2048);

    while (true) {
        __syncthreads();
        if (t == 0) s_u = atomicAdd(&g_unit, 1);
        __syncthreads();
        int u = s_u;
        if (u >= NUNITS) break;

        const int tile = u >> 2;
        const int kb   = (u & 3) << 8;
        const int bb   = tile >> 4;
        const int hw0  = (tile & 15) << 6;
        const float* zbase = z + ((long)bb << 18) + hw0;

        float zn2p[8];
        #pragma unroll
        for (int j = 0; j < 8; j++) {
            int px = (j < 4) ? (pxA + j) : (pxB + j - 4);
            zn2p[j] = g_zn2[tile * 64 + px];
        }

        u64 acc[4][8];
        #pragma unroll
        for (int pp = 0; pp < 4; pp++)
            #pragma unroll
            for (int j = 0; j < 8; j++) acc[pp][j] = 0ull;

        fill_stage(sm32, zbase, emb, kb, 0, 0, t);
        asm volatile("cp.async.commit_group;" ::: "memory");

        for (int s = 0; s < 8; s++) {
            asm volatile("cp.async.wait_group 0;" ::: "memory");
            __syncthreads();
            if (s < 7) {
                fill_stage(sm32, zbase, emb, kb, (s + 1) << 5, (s + 1) & 1, t);
                asm volatile("cp.async.commit_group;" ::: "memory");
            }
            const int b = s & 1;
            compute_stage(smem + (b ? ZS1 : ZS0), smem + ES0 + b * ESB + kg * 36,
                          pxA, pxB, acc);
        }

        float bestv[8];
        int   besti[8];
        #pragma unroll
        for (int i = 0; i < 8; i++) { bestv[i] = 3.402823466e38f; besti[i] = 0x7fffffff; }
        #pragma unroll
        for (int j = 0; j < 8; j++) {
            int code = kb + kg + 32 * j;
            float e2 = g_en2[code];
            #pragma unroll
            for (int pp = 0; pp < 4; pp++) {
                float lo, hi;
                asm("mov.b64 {%0, %1}, %2;" : "=f"(lo), "=f"(hi) : "l"(acc[pp][j]));
                int i2 = pp * 2;
                float s0 = __fadd_rn(zn2p[i2],     e2);
                float s1 = __fadd_rn(zn2p[i2 + 1], e2);
                float v0 = __fadd_rn(s0, __fmul_rn(-2.0f, lo));
                float v1 = __fadd_rn(s1, __fmul_rn(-2.0f, hi));
                if (v0 < bestv[i2])     { bestv[i2]     = v0; besti[i2]     = code; }
                if (v1 < bestv[i2 + 1]) { bestv[i2 + 1] = v1; besti[i2 + 1] = code; }
            }
        }

        __syncthreads();
        #pragma unroll
        for (int j = 0; j < 8; j++) {
            int px = (j < 4) ? (pxA + j) : (pxB + j - 4);
            redv[kg * 64 + px] = bestv[j];
            redi[kg * 64 + px] = besti[j];
        }
        __syncthreads();
        if (t < 64) {
            float bv = redv[t];
            int   bi = redi[t];
            #pragma unroll 4
            for (int g = 1; g < 32; g++) {
                float v = redv[g * 64 + t];
                int   i = redi[g * 64 + t];
                if (v < bv || (v == bv && i < bi)) { bv = v; bi = i; }
            }
            int n = tile * 64 + t;
            g_bestv[n * 4 + (u & 3)] = bv;
            g_besti[n * 4 + (u & 3)] = bi;
        }
    }
}

// ---------------------------------------------------------------------------
// Kernel 3: cross-kb final argmin + gather + STE + loss partials + fused
// last-block final loss reduction. 1024 blocks x 32 px (high occupancy),
// conflict-free emb staging.
// ---------------------------------------------------------------------------
#define GSTR 259
__global__ __launch_bounds__(256) void vq_gather(const float* __restrict__ z,
                                                 const float* __restrict__ emb,
                                                 float* __restrict__ outz,
                                                 float* __restrict__ out_idx,
                                                 float* __restrict__ out_all) {
    extern __shared__ float srows[];           // [32][GSTR]
    __shared__ int idxs[32];
    __shared__ float ws[8];
    __shared__ int lastflag;
    int t = threadIdx.x, blk = blockIdx.x;
    int bb = blk >> 5, hw0 = (blk & 31) << 5;

    if (t < 32) {
        int n = blk * 32 + t;                  // == bb*HWQ + hw0 + t
        float bv = g_bestv[n * 4];
        int   bi = g_besti[n * 4];
        #pragma unroll
        for (int s = 1; s < 4; s++) {          // ascending kb, strict < => lowest idx
            float v = g_bestv[n * 4 + s];
            int   i = g_besti[n * 4 + s];
            if (v < bv) { bv = v; bi = i; }
        }
        idxs[t] = bi;
        out_idx[n] = (float)bi;
    }
    __syncthreads();
    {   // stage 32 emb rows; interleaved float4 layout -> 32 distinct banks
        int r = t >> 3, part = t & 7;
        const float4* er = (const float4*)(emb + (long)idxs[r] * CQ);
        float* d = srows + r * GSTR;
        #pragma unroll
        for (int i = 0; i < 8; i++) {
            float4 v = er[part + i * 8];
            int c = (part + i * 8) * 4;
            d[c] = v.x; d[c + 1] = v.y; d[c + 2] = v.z; d[c + 3] = v.w;
        }
    }
    __syncthreads();
    int px = t & 31, c0 = t >> 5;              // 8 c-groups
    const float* zb = z + ((long)bb << 18) + hw0;
    float* ob = outz + ((long)bb << 18) + hw0;
    float acc = 0.0f;
    #pragma unroll 8
    for (int i = 0; i < 32; i++) {
        int c = i * 8 + c0;
        float zv = zb[(long)c * HWQ + px];
        float qv = srows[px * GSTR + c];
        float d0 = __fadd_rn(qv, -zv);
        ob[(long)c * HWQ + px] = __fadd_rn(zv, d0);     // == z + sg(z_q - z)
        acc = fmaf(d0, d0, acc);
    }
    #pragma unroll
    for (int off = 16; off; off >>= 1)
        acc += __shfl_xor_sync(0xffffffffu, acc, off);
    if ((t & 31) == 0) ws[t >> 5] = acc;
    __syncthreads();
    if (t == 0) {
        float tot = 0.0f;
        #pragma unroll
        for (int i = 0; i < 8; i++) tot += ws[i];
        g_part[blk] = tot;
        __threadfence();
        lastflag = (atomicAdd(&g_done, 1) == 1023);
    }
    __syncthreads();
    if (lastflag) {                            // final deterministic loss
        __shared__ double red[256];
        double s = 0.0;
        for (int i = t; i < 1024; i += 256) s += (double)g_part[i];
        red[t] = s;
        __syncthreads();
        for (int st = 128; st; st >>= 1) {
            if (t < st) red[t] += red[t + st];
            __syncthreads();
        }
        if (t == 0) {
            float m = (float)(red[0] / 8388608.0);
            out_all[ZQ_ELEMS + NPX] = 0.25f * m + m;
        }
    }
}

// ---------------------------------------------------------------------------
extern "C" void kernel_launch(void* const* d_in, const int* in_sizes, int n_in,
                              void* d_out, int out_size) {
    const float* z   = (const float*)d_in[0];
    const float* emb = (const float*)d_in[1];
    float* out = (float*)d_out;

    cudaFuncSetAttribute(vq_unit, cudaFuncAttributeMaxDynamicSharedMemorySize,
                         SMEM_BYTES);
    cudaFuncSetAttribute(vq_gather, cudaFuncAttributeMaxDynamicSharedMemorySize,
                         32 * GSTR * 4);

    vq_pre<<<136, 256>>>(emb, z);
    vq_unit<<<NWORK, 256, SMEM_BYTES>>>(z, emb);
    vq_gather<<<1024, 256, 32 * GSTR * 4>>>(z, emb, out, out + ZQ_ELEMS, out);
}